// round 14
// baseline (speedup 1.0000x reference)
#include <cuda_runtime.h>

#define NP 16384   // N_POINTS
#define NS 8192    // N_SAMPLES
#define KCHUNK 128
#define NKCH (NS / KCHUNK)   // 64 k-chunks
#define TPB 256
#define IPT 4
#define IBLK (TPB * IPT)     // 1024 i-points per tile
#define NIB (NS / IBLK)      // 8 i-tiles -> grid 8 x 64 = 512

typedef unsigned long long u64;

// Scratch (no device allocations). Counters self-reset each run (graph-safe).
__device__ float4   g_a[NS];               // (ax, ay, az, ||a||^2)
__device__ float4   g_b[NS];               // (-2bx, -2by, -2bz, ||b||^2)
__device__ float    g_partial[NKCH * NS];  // [kchunk][i] partial mins
__device__ unsigned g_tile_ctr[NIB];       // static zero-init

__device__ __forceinline__ u64 pack2(float lo, float hi) {
    u64 r;
    asm("mov.b64 %0, {%1, %2};" : "=l"(r) : "f"(lo), "f"(hi));
    return r;
}
__device__ __forceinline__ void unpack2(u64 v, float& lo, float& hi) {
    asm("mov.b64 {%0, %1}, %2;" : "=f"(lo), "=f"(hi) : "l"(v));
}
__device__ __forceinline__ u64 fma2(u64 a, u64 b, u64 c) {
    u64 d;
    asm("fma.rn.f32x2 %0, %1, %2, %3;" : "=l"(d) : "l"(a), "l"(b), "l"(c));
    return d;
}

__global__ void gather_kernel(const float* __restrict__ a,
                              const float* __restrict__ b,
                              const int* __restrict__ a_idx,
                              const int* __restrict__ b_idx,
                              float* __restrict__ out) {
    int i = blockIdx.x * blockDim.x + threadIdx.x;
    if (i == 0) *out = 0.0f;   // d_out is poisoned; reducers atomicAdd into it
    if (i >= NS) return;

    int ia = a_idx[i];
    float ax = a[ia], ay = a[NP + ia], az = a[2 * NP + ia];
    g_a[i] = make_float4(ax, ay, az, ax * ax + ay * ay + az * az);

    int ib = b_idx[i];
    float bx = b[ib], by = b[NP + ib], bz = b[2 * NP + ib];
    g_b[i] = make_float4(-2.0f * bx, -2.0f * by, -2.0f * bz,
                         bx * bx + by * by + bz * bz);
}

__global__ __launch_bounds__(TPB, 4) void dist_kernel(float* __restrict__ out) {
    // SoA so two consecutive k's load as one broadcast LDS.64
    __shared__ __align__(8) float sbx[KCHUNK], sby[KCHUNK], sbz[KCHUNK], sbw[KCHUNK];
    __shared__ float ssum[TPB / 32];
    __shared__ int s_last;

    const int t = threadIdx.x;
    const int it = blockIdx.x;   // i-tile 0..NIB-1
    const int kq = blockIdx.y;   // k-chunk 0..NKCH-1
    const int ibase = it * IBLK + t;

    if (t < KCHUNK) {   // coalesced packed-b stage
        float4 v = g_b[kq * KCHUNK + t];
        sbx[t] = v.x; sby[t] = v.y; sbz[t] = v.z; sbw[t] = v.w;
    }

    u64 ax2[IPT], ay2[IPT], az2[IPT];
    float sqa[IPT], mn_e[IPT], mn_o[IPT];
    #pragma unroll
    for (int r = 0; r < IPT; r++) {       // coalesced packed-a loads
        float4 v = g_a[ibase + r * TPB];
        ax2[r] = pack2(v.x, v.x);
        ay2[r] = pack2(v.y, v.y);
        az2[r] = pack2(v.z, v.z);
        sqa[r] = v.w;
        mn_e[r] = 3.4e38f; mn_o[r] = 3.4e38f;
    }
    __syncthreads();

    #pragma unroll 8
    for (int k = 0; k < KCHUNK; k += 2) {
        u64 bx2 = *reinterpret_cast<const u64*>(&sbx[k]);
        u64 by2 = *reinterpret_cast<const u64*>(&sby[k]);
        u64 bz2 = *reinterpret_cast<const u64*>(&sbz[k]);
        u64 bw2 = *reinterpret_cast<const u64*>(&sbw[k]);
        #pragma unroll
        for (int r = 0; r < IPT; r++) {
            // two k's at once: ||b||^2 - 2 b.a  (||a||^2 added at the end)
            u64 d2 = fma2(bx2, ax2[r], fma2(by2, ay2[r], fma2(bz2, az2[r], bw2)));
            float dl, dh;
            unpack2(d2, dl, dh);
            mn_e[r] = fminf(mn_e[r], dl);
            mn_o[r] = fminf(mn_o[r], dh);
        }
    }

    #pragma unroll
    for (int r = 0; r < IPT; r++)   // coalesced partial writes
        g_partial[kq * NS + ibase + r * TPB] = fminf(mn_e[r], mn_o[r]) + sqa[r];

    // ---- last block of this i-tile reduces the tile and adds to out ----
    __threadfence();
    __syncthreads();
    if (t == 0) {
        unsigned old = atomicAdd(&g_tile_ctr[it], 1u);
        s_last = (old == NKCH - 1);
    }
    __syncthreads();
    if (!s_last) return;

    __threadfence();
    float v = 0.0f;
    #pragma unroll
    for (int r = 0; r < IPT; r++) {
        int i = ibase + r * TPB;
        float m = g_partial[i];
        #pragma unroll
        for (int c = 1; c < NKCH; c++)     // 64 independent LDGs, high MLP
            m = fminf(m, g_partial[c * NS + i]);
        v += m;
    }
    #pragma unroll
    for (int o = 16; o > 0; o >>= 1)
        v += __shfl_down_sync(0xffffffffu, v, o);
    if ((t & 31) == 0) ssum[t >> 5] = v;
    __syncthreads();
    if (t == 0) {
        float s = 0.0f;
        #pragma unroll
        for (int w = 0; w < TPB / 32; w++) s += ssum[w];
        g_tile_ctr[it] = 0;         // reset for next graph replay
        atomicAdd(out, s);
    }
}

extern "C" void kernel_launch(void* const* d_in, const int* in_sizes, int n_in,
                              void* d_out, int out_size) {
    const float* a  = (const float*)d_in[0];
    const float* b  = (const float*)d_in[1];
    const int*   ai = (const int*)d_in[2];
    const int*   bi = (const int*)d_in[3];
    float* out = (float*)d_out;

    gather_kernel<<<(NS + 255) / 256, 256>>>(a, b, ai, bi, out);
    dist_kernel<<<dim3(NIB, NKCH), TPB>>>(out);
}

// round 17
// speedup vs baseline: 1.0097x; 1.0097x over previous
#include <cuda_runtime.h>

#define NP 16384   // N_POINTS
#define NS 8192    // N_SAMPLES
#define KCHUNK 256
#define NKCH (NS / KCHUNK)   // 32 k-chunks
#define TPB 256
#define IPT 4
#define IBLK (TPB * IPT)     // 1024 i-points per tile
#define NIB (NS / IBLK)      // 8 i-tiles -> grid 8 x 32 = 256

// Scratch (no device allocations). Counters self-reset each run (graph-safe).
__device__ float4   g_a[NS];               // (ax, ay, az, ||a||^2)
__device__ float4   g_b[NS];               // (-2bx, -2by, -2bz, ||b||^2)
__device__ float    g_partial[NKCH * NS];  // [kchunk][i] partial mins
__device__ unsigned g_tile_ctr[NIB];       // static zero-init

__global__ void gather_kernel(const float* __restrict__ a,
                              const float* __restrict__ b,
                              const int* __restrict__ a_idx,
                              const int* __restrict__ b_idx,
                              float* __restrict__ out) {
    int i = blockIdx.x * blockDim.x + threadIdx.x;
    if (i == 0) *out = 0.0f;   // d_out is poisoned; reducers atomicAdd into it
    if (i >= NS) return;

    int ia = a_idx[i];
    float ax = a[ia], ay = a[NP + ia], az = a[2 * NP + ia];
    g_a[i] = make_float4(ax, ay, az, ax * ax + ay * ay + az * az);

    int ib = b_idx[i];
    float bx = b[ib], by = b[NP + ib], bz = b[2 * NP + ib];
    g_b[i] = make_float4(-2.0f * bx, -2.0f * by, -2.0f * bz,
                         bx * bx + by * by + bz * bz);
}

__global__ __launch_bounds__(TPB) void dist_kernel(float* __restrict__ out) {
    __shared__ float4 sb[KCHUNK];      // (-2bx,-2by,-2bz,||b||^2), broadcast reads
    __shared__ float ssum[TPB / 32];
    __shared__ int s_last;

    const int t = threadIdx.x;
    const int it = blockIdx.x;   // i-tile 0..NIB-1
    const int kq = blockIdx.y;   // k-chunk 0..NKCH-1
    const int ibase = it * IBLK + t;

    sb[t] = g_b[kq * KCHUNK + t];      // coalesced packed-b stage

    float ax[IPT], ay[IPT], az[IPT], sqa[IPT], mn[IPT];
    #pragma unroll
    for (int r = 0; r < IPT; r++) {    // coalesced packed-a loads
        float4 v = g_a[ibase + r * TPB];
        ax[r] = v.x; ay[r] = v.y; az[r] = v.z; sqa[r] = v.w;
        mn[r] = 3.4e38f;
    }
    __syncthreads();

    // Scalar mainloop: 3 FFMA (fma pipe) + 1 FMNMX (alu pipe) per pair.
    // 4 independent chains (IPT) x unroll keeps the fma pipe saturated at rt=2.
    #pragma unroll 4
    for (int k = 0; k < KCHUNK; k++) {
        float4 bv = sb[k];             // one broadcast LDS.128
        #pragma unroll
        for (int r = 0; r < IPT; r++) {
            // ||b||^2 - 2 b.a   (||a||^2 added at the end)
            float d = fmaf(bv.x, ax[r], fmaf(bv.y, ay[r], fmaf(bv.z, az[r], bv.w)));
            mn[r] = fminf(mn[r], d);
        }
    }

    #pragma unroll
    for (int r = 0; r < IPT; r++)      // coalesced partial writes
        g_partial[kq * NS + ibase + r * TPB] = mn[r] + sqa[r];

    // ---- last block of this i-tile reduces the tile and adds to out ----
    __threadfence();
    __syncthreads();
    if (t == 0) {
        unsigned old = atomicAdd(&g_tile_ctr[it], 1u);
        s_last = (old == NKCH - 1);
    }
    __syncthreads();
    if (!s_last) return;

    __threadfence();
    float v = 0.0f;
    #pragma unroll
    for (int r = 0; r < IPT; r++) {
        int i = ibase + r * TPB;
        float m = g_partial[i];
        #pragma unroll
        for (int c = 1; c < NKCH; c++)     // 32 independent LDGs, high MLP
            m = fminf(m, g_partial[c * NS + i]);
        v += m;
    }
    #pragma unroll
    for (int o = 16; o > 0; o >>= 1)
        v += __shfl_down_sync(0xffffffffu, v, o);
    if ((t & 31) == 0) ssum[t >> 5] = v;
    __syncthreads();
    if (t == 0) {
        float s = 0.0f;
        #pragma unroll
        for (int w = 0; w < TPB / 32; w++) s += ssum[w];
        g_tile_ctr[it] = 0;         // reset for next graph replay
        atomicAdd(out, s);
    }
}

extern "C" void kernel_launch(void* const* d_in, const int* in_sizes, int n_in,
                              void* d_out, int out_size) {
    const float* a  = (const float*)d_in[0];
    const float* b  = (const float*)d_in[1];
    const int*   ai = (const int*)d_in[2];
    const int*   bi = (const int*)d_in[3];
    float* out = (float*)d_out;

    gather_kernel<<<(NS + 255) / 256, 256>>>(a, b, ai, bi, out);
    dist_kernel<<<dim3(NIB, NKCH), TPB>>>(out);
}